// round 6
// baseline (speedup 1.0000x reference)
#include <cuda_runtime.h>
#include <cuda_bf16.h>
#include <cstdint>

// Problem constants
#define Bsz   64
#define Lsz   64
#define Hsz   128
#define Ssz   64
#define INsz  16

// c history: [s][b][h]
__device__ float g_chist[Ssz * Bsz * Hsz];

// ---------------- helpers ----------------
__device__ __forceinline__ uint32_t smem_u32(const void* p) {
    uint32_t a;
    asm("{ .reg .u64 t; cvta.to.shared.u64 t, %1; cvt.u32.u64 %0, t; }"
        : "=r"(a) : "l"(p));
    return a;
}
__device__ __forceinline__ uint32_t mapa_rank(uint32_t laddr, uint32_t rk) {
    uint32_t ra;
    asm("mapa.shared::cluster.u32 %0, %1, %2;" : "=r"(ra) : "r"(laddr), "r"(rk));
    return ra;
}
__device__ __forceinline__ void st_cluster_b64(uint32_t addr, uint64_t v) {
    asm volatile("st.shared::cluster.b64 [%0], %1;" :: "r"(addr), "l"(v) : "memory");
}
__device__ __forceinline__ uint32_t cluster_rank() {
    uint32_t r; asm("mov.u32 %0, %%cluster_ctarank;" : "=r"(r)); return r;
}
__device__ __forceinline__ void cluster_sync() {
    asm volatile("barrier.cluster.arrive.aligned;" ::: "memory");
    asm volatile("barrier.cluster.wait.aligned;" ::: "memory");
}
__device__ __forceinline__ float sigf(float x) {
    return __fdividef(1.0f, 1.0f + __expf(-x));
}
__device__ __forceinline__ float tanh_acc(float x) {
    return __fmaf_rn(2.0f, sigf(2.0f * x), -1.0f);
}
__device__ __forceinline__ uint64_t pack2(float lo, float hi) {
    uint64_t r; asm("mov.b64 %0, {%1, %2};" : "=l"(r) : "f"(lo), "f"(hi)); return r;
}
__device__ __forceinline__ void fma2(uint64_t& d, uint64_t a, uint64_t b) {
    asm("fma.rn.f32x2 %0, %1, %2, %0;" : "+l"(d) : "l"(a), "l"(b));
}
__device__ __forceinline__ void mbar_arrive_remote(uint32_t raddr) {
    asm volatile("mbarrier.arrive.release.cluster.shared::cluster.b64 _, [%0];"
                 :: "r"(raddr) : "memory");
}
__device__ __forceinline__ void mbar_wait(uint32_t addr, uint32_t parity) {
    uint32_t done;
    asm volatile(
        "{\n\t.reg .pred p;\n\t"
        "mbarrier.try_wait.parity.acquire.cluster.shared::cta.b64 p, [%1], %2;\n\t"
        "selp.b32 %0, 1, 0, p;\n\t}"
        : "=r"(done) : "r"(addr), "r"(parity) : "memory");
    if (!done) {
        asm volatile(
            "{\n\t.reg .pred P1;\n\t"
            "WAIT_LOOP_%=:\n\t"
            "mbarrier.try_wait.parity.acquire.cluster.shared::cta.b64 P1, [%0], %1, 0x989680;\n\t"
            "@P1 bra.uni WAIT_DONE_%=;\n\t"
            "bra.uni WAIT_LOOP_%=;\n\t"
            "WAIT_DONE_%=:\n\t}"
            :: "r"(addr), "r"(parity) : "memory");
    }
}

// ---------------- kernel 1: recurrence ----------------
// 128 CTAs = 32 clusters x 4. Cluster ci: batches {2ci, 2ci+1}.
// CTA rank r: h-tile [32r, 32r+32) => W cols {g*128 + 32r + hh}.
// W slice lives in REGISTERS: thread (kq=tid>>5, j4=tid&31) holds
// W[k in 32kq..+32)][jl in 4*j4..+4) as 64 packed f32x2 pairs (j-pairs).
// State is kept DUPLICATED in smem (float2 (v,v)) so fma.rn.f32x2 needs no movs.
extern "C" __global__ void __cluster_dims__(4, 1, 1) __launch_bounds__(256, 1)
lstm_recur_kernel(const float* __restrict__ emb,
                  const float* __restrict__ Wg,
                  const float* __restrict__ bg)
{
    __shared__ float2 inpd[2 * 2 * 256];        // [buf][b][k], dup pairs (8 KB)
    __shared__ float  gpart[8 * 2 * 128];       // [q][b][jl]   (8 KB)
    __shared__ float  gs[2 * 128];              // activated gates
    __shared__ float  bias_s[128];
    __shared__ __align__(8) uint64_t mbar;

    const int tid = threadIdx.x;
    const uint32_t r = cluster_rank();
    const int b0 = (blockIdx.x >> 2) * 2;

    const int j4 = tid & 31;
    const int kq = tid >> 5;
    const int jl0 = j4 * 4;

    // ---- W slice to registers, packed as j-pairs ----
    uint64_t wp[64];
    {
        const int jg0 = ((jl0 >> 5) << 7) + (int)(r << 5) + (jl0 & 31);
        #pragma unroll
        for (int kk = 0; kk < 32; ++kk) {
            const float4 w4 = *(const float4*)(Wg + (size_t)(kq * 32 + kk) * 512 + jg0);
            wp[2 * kk]     = pack2(w4.x, w4.y);
            wp[2 * kk + 1] = pack2(w4.z, w4.w);
        }
    }
    if (tid < 128)
        bias_s[tid] = bg[((tid >> 5) << 7) + (int)(r << 5) + (tid & 31)];

    // ---- init inpd[0] = dup([emb[:,0,:], zeros]) ----
    for (int idx = tid; idx < 512; idx += 256) {
        int b = idx >> 8, k = idx & 255;
        float v = (k < 128) ? emb[(size_t)(b0 + b) * (Lsz * Hsz) + k] : 0.0f;
        inpd[idx] = make_float2(v, v);
    }
    if (tid == 0) {
        asm volatile("mbarrier.init.shared.b64 [%0], 256;"
                     :: "r"(smem_u32(&mbar)) : "memory");
    }
    __syncthreads();
    cluster_sync();   // mbar init + inpd visible cluster-wide before any remote op

    // ---- precompute remote addresses (mapa is offset-preserving) ----
    const uint32_t mbar_l = smem_u32(&mbar);
    const uint32_t inpd_l = smem_u32(&inpd[0]);
    uint32_t mbar_r[4], inpd_r[4];
    #pragma unroll
    for (int pr = 0; pr < 4; ++pr) {
        mbar_r[pr] = mapa_rank(mbar_l, (uint32_t)pr);
        inpd_r[pr] = mapa_rank(inpd_l, (uint32_t)pr);
    }

    const int hh = tid & 31;   // update role (tid < 64)
    const int ub = tid >> 5;
    float c_old = 0.0f;

    uint64_t* gp8 = (uint64_t*)gpart;

    for (int t = 0; t < Ssz; ++t) {
        const int cur = t & 1, nxt = cur ^ 1;

        // ---- GEMM: 32 k-iters, 4 f32x2 FMA each (j-pairs x 2 batches) ----
        const uint64_t* ip0 = (const uint64_t*)(inpd + cur * 512) + kq * 32; // b=0
        const uint64_t* ip1 = ip0 + 256;                                     // b=1
        uint64_t a00 = 0, a01 = 0, a10 = 0, a11 = 0;
        #pragma unroll
        for (int kk = 0; kk < 32; ++kk) {
            uint64_t x0 = ip0[kk];
            uint64_t x1 = ip1[kk];
            fma2(a00, wp[2 * kk], x0);
            fma2(a01, wp[2 * kk + 1], x0);
            fma2(a10, wp[2 * kk], x1);
            fma2(a11, wp[2 * kk + 1], x1);
        }
        // gpart[q][b][jl] (u64 units: q*128 + b*64 + jl/2)
        const uint32_t gb = (uint32_t)(kq * 128 + (jl0 >> 1));
        gp8[gb]          = a00;
        gp8[gb + 1]      = a01;
        gp8[gb + 64]     = a10;
        gp8[gb + 64 + 1] = a11;
        __syncthreads();

        // ---- reduce + activation: one thread per (b, gate-col) ----
        {
            const int b = tid >> 7, jl = tid & 127;
            float v = bias_s[jl];
            #pragma unroll
            for (int q = 0; q < 8; ++q)
                v += gpart[q * 256 + b * 128 + jl];
            gs[b * 128 + jl] = (jl < 96) ? sigf(v) : tanh_acc(v);
        }
        __syncthreads();

        // ---- combine + state scatter (tid < 64) ----
        if (tid < 64) {
            const float* g = gs + ub * 128;
            float f = g[hh], iv = g[32 + hh], ov = g[64 + hh], cd = g[96 + hh];
            float cn = __fmaf_rn(f, c_old, iv * cd);
            float hn = ov * tanh_acc(cn);
            c_old = cn;

            const int hglob = (int)(r << 5) + hh;
            g_chist[((t << 6) + (b0 + ub)) * 128 + hglob] = cn;

            if (t < Ssz - 1) {
                const uint64_t cnd = pack2(cn, cn);
                const uint64_t hnd = pack2(hn, hn);
                const uint32_t off_c = (uint32_t)(nxt * 512 + ub * 256 + hglob) * 8u;
                #pragma unroll
                for (int pr = 0; pr < 4; ++pr) {
                    st_cluster_b64(inpd_r[pr] + off_c, cnd);
                    st_cluster_b64(inpd_r[pr] + off_c + 128 * 8, hnd);
                }
                #pragma unroll
                for (int pr = 0; pr < 4; ++pr)
                    mbar_arrive_remote(mbar_r[pr]);
            }
        }
        if (t < Ssz - 1)
            mbar_wait(mbar_l, (uint32_t)(t & 1));
    }
}

// ---------------- kernel 2: projection + broadcast write ----------------
extern "C" __global__ void __launch_bounds__(128)
proj_kernel(const float* __restrict__ Wlin,
            const float* __restrict__ blin,
            float* __restrict__ out)
{
    __shared__ float sc[128];
    __shared__ float pred[8][16];
    __shared__ float pv[16];

    const int bs = blockIdx.x;
    const int b = bs >> 6, s = bs & 63;
    const int tid = threadIdx.x;

    sc[tid] = g_chist[((s << 6) + b) * 128 + tid];
    __syncthreads();

    const int o = tid & 15, hq = tid >> 4;
    float acc = 0.0f;
    #pragma unroll
    for (int u = 0; u < 16; ++u) {
        int h = (hq << 4) + u;
        acc = __fmaf_rn(sc[h], Wlin[h * 16 + o], acc);
    }
    pred[hq][o] = acc;
    __syncthreads();

    if (tid < 16) {
        float v = blin[tid];
        #pragma unroll
        for (int q = 0; q < 8; ++q) v += pred[q][tid];
        pv[tid] = v;
    }
    __syncthreads();

    float4* dst = (float4*)(out + 262144) + (size_t)((b << 12) + (s << 6)) * 4;
    int c0 = (tid & 3) << 2;
    float4 val = make_float4(pv[c0], pv[c0 + 1], pv[c0 + 2], pv[c0 + 3]);
    dst[tid]       = val;
    dst[tid + 128] = val;
}

// ---------------- kernel 3: trip passthrough copy ----------------
extern "C" __global__ void __launch_bounds__(256)
trip_copy_kernel(const float4* __restrict__ in, float4* __restrict__ out)
{
    int i = blockIdx.x * 256 + threadIdx.x;
    out[i] = in[i];
}

// ---------------- launch ----------------
extern "C" void kernel_launch(void* const* d_in, const int* in_sizes, int n_in,
                              void* d_out, int out_size)
{
    const float* trip = (const float*)d_in[0];
    // d_in[1] = valid_len (unused by reference)
    const float* emb  = (const float*)d_in[2];
    const float* Wg   = (const float*)d_in[3];
    const float* bg   = (const float*)d_in[4];
    const float* Wl   = (const float*)d_in[5];
    const float* bl   = (const float*)d_in[6];
    float* out = (float*)d_out;

    lstm_recur_kernel<<<128, 256>>>(emb, Wg, bg);
    proj_kernel<<<Bsz * Ssz, 128>>>(Wl, bl, out);
    trip_copy_kernel<<<256, 256>>>((const float4*)trip, (float4*)out);
}